// round 1
// baseline (speedup 1.0000x reference)
#include <cuda_runtime.h>
#include <math.h>

#define BB   16
#define CC   96
#define C4   384
#define HH   56
#define WW   56
#define HWP  3136          // 56*56
#define CHW  301056        // 96*3136

// ---------------- scratch (device globals; no allocation) ----------------
__device__ float g_buf1[BB * CC * HWP];   // dw out, then normalized h
__device__ float g_buf2[BB * CC * HWP];   // pw out (pre-LN)
__device__ float g_buf3[BB * C4 * HWP];   // expand+gelu out
__device__ float g_stats[BB * 2];         // mu, rstd per batch
__device__ float g_sv[BB * C4];           // top singular values
__device__ float g_svsum;                 // sum of all sv

// ---------------- helpers ----------------
__device__ __forceinline__ float gelu_tanh_f(float x) {
    const float c = 0.7978845608028654f;
    float x3 = x * x * x;
    return 0.5f * x * (1.0f + tanhf(c * (x + 0.044715f * x3)));
}

// ---------------- 1) depthwise 7x7 conv + bias ----------------
// grid: (1, 7, B*C), block: (56, 8)
__global__ void dw_conv_kernel(const float* __restrict__ x,
                               const float* __restrict__ dw_w,
                               const float* __restrict__ dw_b) {
    __shared__ float tile[14][62];   // 8+6 rows, 56+6 cols
    __shared__ float sw[49];

    const int bc = blockIdx.z;           // b*C + c
    const int c  = bc % CC;
    const int y0 = blockIdx.y * 8;
    const int tx = threadIdx.x;          // 0..55
    const int ty = threadIdx.y;          // 0..7
    const int tid = ty * 56 + tx;

    const float* src = x + (size_t)bc * HWP;

    if (tid < 49) sw[tid] = dw_w[c * 49 + tid];

    // cooperative halo load: 14*62 = 868 elements, 448 threads
    for (int i = tid; i < 14 * 62; i += 448) {
        int r  = i / 62;
        int cx = i - r * 62;
        int gy = y0 - 3 + r;
        int gx = cx - 3;
        float v = 0.0f;
        if (gy >= 0 && gy < HH && gx >= 0 && gx < WW) v = src[gy * WW + gx];
        tile[r][cx] = v;
    }
    __syncthreads();

    float acc = dw_b[c];
    #pragma unroll
    for (int dy = 0; dy < 7; dy++) {
        #pragma unroll
        for (int dx = 0; dx < 7; dx++) {
            acc = fmaf(sw[dy * 7 + dx], tile[ty + dy][tx + dx], acc);
        }
    }
    g_buf1[(size_t)bc * HWP + (y0 + ty) * WW + tx] = acc;
}

// ---------------- 2/5/8) channel GEMM: out[b,m,n] = sum_k W[m,k]*in[b,k,n] ----------------
// MODE 0: +bias                  (pointwise)
// MODE 1: +bias, gelu            (expand)
// MODE 2: in scaled by GRN affine, +bias, +residual   (project)
// grid: (HW/64, M/96, B), block: 256
template <int MODE>
__global__ void gemm_chan(const float* __restrict__ W,
                          const float* __restrict__ bias,
                          const float* __restrict__ in,
                          float* __restrict__ out,
                          int M, int K,
                          const float* __restrict__ gamma,
                          const float* __restrict__ beta,
                          const float* __restrict__ resid) {
    const int BM = 96, BN = 64, BK = 32;
    __shared__ float As[32][97];   // [kk][m], padded
    __shared__ float Bs[32][64];   // [kk][n]

    const int n0 = blockIdx.x * BN;
    const int m0 = blockIdx.y * BM;
    const int b  = blockIdx.z;
    const int tid = threadIdx.x;
    const int tx = tid & 15;       // n dir, *4
    const int ty = tid >> 4;       // m dir, *6

    const float* inb = in + (size_t)b * K * HWP;

    float inv_sum = 0.0f;
    if (MODE == 2) inv_sum = 1.0f / g_svsum;

    float acc[6][4];
    #pragma unroll
    for (int i = 0; i < 6; i++)
        #pragma unroll
        for (int j = 0; j < 4; j++) acc[i][j] = 0.0f;

    for (int k0 = 0; k0 < K; k0 += BK) {
        // load A tile (96x32), coalesced over K, transposed into smem
        #pragma unroll
        for (int i = tid; i < BM * BK; i += 256) {
            int m  = i >> 5;
            int kk = i & 31;
            As[kk][m] = W[(size_t)(m0 + m) * K + k0 + kk];
        }
        // load B tile (32x64), coalesced over n
        #pragma unroll
        for (int i = tid; i < BK * BN; i += 256) {
            int kk = i >> 6;
            int n  = i & 63;
            int k  = k0 + kk;
            float v = inb[(size_t)k * HWP + n0 + n];
            if (MODE == 2) {
                int idx = b * C4 + k;
                float s = fmaf(gamma[idx] * g_sv[idx], inv_sum, 1.0f);
                v = fmaf(v, s, beta[idx]);
            }
            Bs[kk][n] = v;
        }
        __syncthreads();

        #pragma unroll
        for (int kk = 0; kk < BK; kk++) {
            float4 b4 = *reinterpret_cast<const float4*>(&Bs[kk][tx * 4]);
            float a[6];
            #pragma unroll
            for (int i = 0; i < 6; i++) a[i] = As[kk][ty * 6 + i];
            #pragma unroll
            for (int i = 0; i < 6; i++) {
                acc[i][0] = fmaf(a[i], b4.x, acc[i][0]);
                acc[i][1] = fmaf(a[i], b4.y, acc[i][1]);
                acc[i][2] = fmaf(a[i], b4.z, acc[i][2]);
                acc[i][3] = fmaf(a[i], b4.w, acc[i][3]);
            }
        }
        __syncthreads();
    }

    // epilogue
    #pragma unroll
    for (int i = 0; i < 6; i++) {
        int m = m0 + ty * 6 + i;
        float bs = bias[m];
        size_t row = ((size_t)b * M + m) * HWP + n0 + tx * 4;
        #pragma unroll
        for (int j = 0; j < 4; j++) {
            float v = acc[i][j] + bs;
            if (MODE == 1) v = gelu_tanh_f(v);
            if (MODE == 2) v += resid[row + j];
            out[row + j] = v;
        }
    }
}

// ---------------- 3) LayerNorm stats (per batch) ----------------
// grid: B, block: 256
__global__ void ln_stats_kernel() {
    __shared__ double s1s[256];
    __shared__ double s2s[256];
    const int b = blockIdx.x;
    const int tid = threadIdx.x;
    const float* src = g_buf2 + (size_t)b * CHW;

    double s1 = 0.0, s2 = 0.0;
    for (int i = tid; i < CHW; i += 256) {
        double v = (double)src[i];
        s1 += v;
        s2 += v * v;
    }
    s1s[tid] = s1; s2s[tid] = s2;
    __syncthreads();
    for (int off = 128; off > 0; off >>= 1) {
        if (tid < off) { s1s[tid] += s1s[tid + off]; s2s[tid] += s2s[tid + off]; }
        __syncthreads();
    }
    if (tid == 0) {
        double mu  = s1s[0] / (double)CHW;
        double var = s2s[0] / (double)CHW - mu * mu;
        g_stats[b * 2 + 0] = (float)mu;
        g_stats[b * 2 + 1] = (float)(1.0 / sqrt(var + 1e-6));
    }
}

// ---------------- 4) LayerNorm apply ----------------
__global__ void ln_apply_kernel(const float* __restrict__ ln_w,
                                const float* __restrict__ ln_b) {
    int idx = blockIdx.x * blockDim.x + threadIdx.x;
    if (idx >= BB * CHW) return;
    int b = idx / CHW;
    int r = idx - b * CHW;
    float mu   = g_stats[b * 2 + 0];
    float rstd = g_stats[b * 2 + 1];
    float v = (g_buf2[idx] - mu) * rstd;
    g_buf1[idx] = fmaf(v, ln_w[r], ln_b[r]);
}

// ---------------- 6) power iteration: top singular value per (b,c4) slice ----------------
// grid: B*C4 = 6144, block: 64
__global__ void power_iter_kernel() {
    __shared__ float sA[56 * 57];   // row-padded to 57 -> conflict free both ways
    __shared__ float sv[56], su[56], sz[56];
    __shared__ float s_nrm;

    const int bc = blockIdx.x;
    const int t  = threadIdx.x;
    const float* src = g_buf3 + (size_t)bc * HWP;

    for (int i = t; i < HWP; i += 64) {
        int r = i / 56, c = i - r * 56;
        sA[r * 57 + c] = src[i];
    }
    if (t < 56) sv[t] = 0.1336306f;   // 1/sqrt(56): unit start vector
    __syncthreads();

    float nz = 0.0f;
    const int ITER = 16;
    for (int it = 0; it < ITER; it++) {
        // u = A v
        if (t < 56) {
            float s = 0.0f;
            #pragma unroll 8
            for (int j = 0; j < 56; j++) s = fmaf(sA[t * 57 + j], sv[j], s);
            su[t] = s;
        }
        __syncthreads();
        // z = A^T u
        if (t < 56) {
            float s = 0.0f;
            #pragma unroll 8
            for (int i = 0; i < 56; i++) s = fmaf(sA[i * 57 + t], su[i], s);
            sz[t] = s;
        }
        __syncthreads();
        if (t == 0) {
            float s = 0.0f;
            for (int j = 0; j < 56; j++) s = fmaf(sz[j], sz[j], s);
            s_nrm = sqrtf(s);
        }
        __syncthreads();
        nz = s_nrm;
        if (t < 56) sv[t] = (nz > 0.0f) ? sz[t] / nz : 0.1336306f;
        __syncthreads();
    }
    if (t == 0) g_sv[bc] = sqrtf(nz);   // ||A^T A v|| -> sigma^2 -> sigma
}

// ---------------- 7) sum of singular values ----------------
__global__ void sv_sum_kernel() {
    __shared__ float s[256];
    const int tid = threadIdx.x;
    float acc = 0.0f;
    for (int i = tid; i < BB * C4; i += 256) acc += g_sv[i];
    s[tid] = acc;
    __syncthreads();
    for (int off = 128; off > 0; off >>= 1) {
        if (tid < off) s[tid] += s[tid + off];
        __syncthreads();
    }
    if (tid == 0) g_svsum = s[0];
}

// ---------------- launch ----------------
extern "C" void kernel_launch(void* const* d_in, const int* in_sizes, int n_in,
                              void* d_out, int out_size) {
    const float* x     = (const float*)d_in[0];
    const float* dw_w  = (const float*)d_in[1];
    const float* dw_b  = (const float*)d_in[2];
    const float* pw_w  = (const float*)d_in[3];
    const float* pw_b  = (const float*)d_in[4];
    const float* ln_w  = (const float*)d_in[5];
    const float* ln_b  = (const float*)d_in[6];
    const float* l1_w  = (const float*)d_in[7];
    const float* l1_b  = (const float*)d_in[8];
    const float* gamma = (const float*)d_in[9];
    const float* beta  = (const float*)d_in[10];
    const float* l2_w  = (const float*)d_in[11];
    const float* l2_b  = (const float*)d_in[12];
    float* out = (float*)d_out;

    float* buf1; cudaGetSymbolAddress((void**)&buf1, g_buf1);
    float* buf2; cudaGetSymbolAddress((void**)&buf2, g_buf2);
    float* buf3; cudaGetSymbolAddress((void**)&buf3, g_buf3);

    // 1) depthwise conv -> buf1
    dw_conv_kernel<<<dim3(1, 7, BB * CC), dim3(56, 8)>>>(x, dw_w, dw_b);

    // 2) pointwise 96->96 -> buf2
    gemm_chan<0><<<dim3(HWP / 64, 1, BB), 256>>>(pw_w, pw_b, buf1, buf2, CC, CC,
                                                 nullptr, nullptr, nullptr);

    // 3) LN stats
    ln_stats_kernel<<<BB, 256>>>();

    // 4) LN apply -> buf1
    {
        int total = BB * CHW;
        ln_apply_kernel<<<(total + 255) / 256, 256>>>(ln_w, ln_b);
    }

    // 5) expand 96->384 + GELU -> buf3
    gemm_chan<1><<<dim3(HWP / 64, C4 / 96, BB), 256>>>(l1_w, l1_b, buf1, buf3, C4, CC,
                                                       nullptr, nullptr, nullptr);

    // 6) top singular value per slice
    power_iter_kernel<<<BB * C4, 64>>>();

    // 7) normalization sum
    sv_sum_kernel<<<1, 256>>>();

    // 8) GRN affine + project 384->96 + bias + residual -> out
    gemm_chan<2><<<dim3(HWP / 64, 1, BB), 256>>>(l2_w, l2_b, buf3, out, CC, C4,
                                                 gamma, beta, x);
}

// round 2
// speedup vs baseline: 1.7448x; 1.7448x over previous
#include <cuda_runtime.h>
#include <math.h>

#define BB   16
#define CC   96
#define C4   384
#define HH   56
#define WW   56
#define HWP  3136          // 56*56
#define CHW  301056        // 96*3136

// ---------------- scratch (device globals; no allocation) ----------------
__device__ float  g_buf1[BB * CC * HWP];   // dw out, then normalized h
__device__ float  g_buf2[BB * CC * HWP];   // pw out (pre-LN)
__device__ float  g_buf3[BB * C4 * HWP];   // expand+gelu out
__device__ double g_red[BB * 2];           // LN sum / sumsq per batch
__device__ float  g_sv[BB * C4];           // top singular values
__device__ float  g_svsum;                 // sum of all sv

// ---------------- helpers ----------------
__device__ __forceinline__ float gelu_tanh_f(float x) {
    const float c = 0.7978845608028654f;
    float x3 = x * x * x;
    return 0.5f * x * (1.0f + tanhf(c * (x + 0.044715f * x3)));
}

__device__ __forceinline__ float tf32r(float x) {
    unsigned u;
    asm("cvt.rna.tf32.f32 %0, %1;" : "=r"(u) : "f"(x));
    return __uint_as_float(u);
}

__device__ __forceinline__ void mma_tf32(float* c, const unsigned* a, const unsigned* b2) {
    asm volatile("mma.sync.aligned.m16n8k8.row.col.f32.tf32.tf32.f32 "
        "{%0,%1,%2,%3}, {%4,%5,%6,%7}, {%8,%9}, {%0,%1,%2,%3};"
        : "+f"(c[0]), "+f"(c[1]), "+f"(c[2]), "+f"(c[3])
        : "r"(a[0]), "r"(a[1]), "r"(a[2]), "r"(a[3]), "r"(b2[0]), "r"(b2[1]));
}

// ---------------- 1) depthwise 7x7 conv + bias (+ scratch zero-init) ----------------
// grid: (1, 7, B*C), block: (56, 8)
__global__ void dw_conv_kernel(const float* __restrict__ x,
                               const float* __restrict__ dw_w,
                               const float* __restrict__ dw_b) {
    __shared__ float tile[14][62];
    __shared__ float sw[49];

    const int bc = blockIdx.z;
    const int c  = bc % CC;
    const int y0 = blockIdx.y * 8;
    const int tx = threadIdx.x;
    const int ty = threadIdx.y;
    const int tid = ty * 56 + tx;

    if (bc == 0 && blockIdx.y == 0) {
        if (tid < BB * 2) g_red[tid] = 0.0;
        if (tid == BB * 2) g_svsum = 0.0f;
    }

    const float* src = x + (size_t)bc * HWP;
    if (tid < 49) sw[tid] = dw_w[c * 49 + tid];

    for (int i = tid; i < 14 * 62; i += 448) {
        int r  = i / 62;
        int cx = i - r * 62;
        int gy = y0 - 3 + r;
        int gx = cx - 3;
        float v = 0.0f;
        if (gy >= 0 && gy < HH && gx >= 0 && gx < WW) v = src[gy * WW + gx];
        tile[r][cx] = v;
    }
    __syncthreads();

    float acc = dw_b[c];
    #pragma unroll
    for (int dy = 0; dy < 7; dy++)
        #pragma unroll
        for (int dx = 0; dx < 7; dx++)
            acc = fmaf(sw[dy * 7 + dx], tile[ty + dy][tx + dx], acc);

    g_buf1[(size_t)bc * HWP + (y0 + ty) * WW + tx] = acc;
}

// ---------------- TF32 tensor-core channel GEMM ----------------
// out[b,m,n] = sum_k W[m,k]*in[b,k,n]
// MODE 0: +bias, fused LN sum/sumsq reduction        (pointwise)
// MODE 1: +bias, gelu                                 (expand)
// MODE 2: B scaled by GRN affine, +bias, +residual    (project)
// grid: (ceil(HW/128), M/96, B), block: 256
template <int MODE>
__global__ __launch_bounds__(256)
void gemm_tc(const float* __restrict__ W,
             const float* __restrict__ bias,
             const float* __restrict__ in,
             float* __restrict__ out,
             int M, int K,
             const float* __restrict__ gamma,
             const float* __restrict__ beta,
             const float* __restrict__ resid) {
    __shared__ float As[32][100];   // [kk][m], 96 used, padded
    __shared__ float Bs[32][132];   // [kk][n], 128 used, padded
    __shared__ double s_red[16];

    const int n0 = blockIdx.x * 128;
    const int m0 = blockIdx.y * 96;
    const int b  = blockIdx.z;
    const int tid  = threadIdx.x;
    const int lane = tid & 31;
    const int warp = tid >> 5;
    const int warp_m = warp >> 2;    // 0..1 -> 48 rows each
    const int warp_n = warp & 3;     // 0..3 -> 32 cols each

    const float* inb = in + (size_t)b * K * HWP;
    const float inv_sum = (MODE == 2) ? (1.0f / g_svsum) : 0.0f;

    float acc[3][4][4];
    #pragma unroll
    for (int mt = 0; mt < 3; mt++)
        #pragma unroll
        for (int nt = 0; nt < 4; nt++)
            #pragma unroll
            for (int j = 0; j < 4; j++) acc[mt][nt][j] = 0.0f;

    for (int k0 = 0; k0 < K; k0 += 32) {
        // stage A (96x32) transposed, tf32-rounded
        #pragma unroll
        for (int i = tid; i < 96 * 8; i += 256) {
            int m = i >> 3;
            int q = i & 7;
            float4 w4 = *reinterpret_cast<const float4*>(&W[(size_t)(m0 + m) * K + k0 + q * 4]);
            As[q * 4 + 0][m] = tf32r(w4.x);
            As[q * 4 + 1][m] = tf32r(w4.y);
            As[q * 4 + 2][m] = tf32r(w4.z);
            As[q * 4 + 3][m] = tf32r(w4.w);
        }
        // stage B (32x128), tf32-rounded; MODE 2 applies GRN affine first
        #pragma unroll
        for (int i = tid; i < 32 * 32; i += 256) {
            int kk = i >> 5;
            int nq = i & 31;
            int gn = n0 + nq * 4;
            float4 v = make_float4(0.f, 0.f, 0.f, 0.f);
            if (gn < HWP) v = *reinterpret_cast<const float4*>(&inb[(size_t)(k0 + kk) * HWP + gn]);
            if (MODE == 2) {
                int idx = b * C4 + k0 + kk;
                float s  = fmaf(gamma[idx] * g_sv[idx], inv_sum, 1.0f);
                float sh = beta[idx];
                v.x = fmaf(v.x, s, sh);
                v.y = fmaf(v.y, s, sh);
                v.z = fmaf(v.z, s, sh);
                v.w = fmaf(v.w, s, sh);
            }
            Bs[kk][nq * 4 + 0] = tf32r(v.x);
            Bs[kk][nq * 4 + 1] = tf32r(v.y);
            Bs[kk][nq * 4 + 2] = tf32r(v.z);
            Bs[kk][nq * 4 + 3] = tf32r(v.w);
        }
        __syncthreads();

        #pragma unroll
        for (int ks = 0; ks < 4; ks++) {
            const int kq = ks * 8 + (lane & 3);
            const int mr = lane >> 2;
            unsigned afr[3][4];
            #pragma unroll
            for (int mt = 0; mt < 3; mt++) {
                int m = warp_m * 48 + mt * 16 + mr;
                afr[mt][0] = __float_as_uint(As[kq][m]);
                afr[mt][1] = __float_as_uint(As[kq][m + 8]);
                afr[mt][2] = __float_as_uint(As[kq + 4][m]);
                afr[mt][3] = __float_as_uint(As[kq + 4][m + 8]);
            }
            unsigned bfr[4][2];
            #pragma unroll
            for (int nt = 0; nt < 4; nt++) {
                int n = warp_n * 32 + nt * 8 + mr;
                bfr[nt][0] = __float_as_uint(Bs[kq][n]);
                bfr[nt][1] = __float_as_uint(Bs[kq + 4][n]);
            }
            #pragma unroll
            for (int mt = 0; mt < 3; mt++)
                #pragma unroll
                for (int nt = 0; nt < 4; nt++)
                    mma_tf32(acc[mt][nt], afr[mt], bfr[nt]);
        }
        __syncthreads();
    }

    // epilogue
    double s1 = 0.0, s2 = 0.0;
    #pragma unroll
    for (int mt = 0; mt < 3; mt++) {
        const int mA = m0 + warp_m * 48 + mt * 16 + (lane >> 2);
        const float biasA = bias[mA];
        const float biasB = bias[mA + 8];
        #pragma unroll
        for (int nt = 0; nt < 4; nt++) {
            const int n = n0 + warp_n * 32 + nt * 8 + 2 * (lane & 3);
            if (n < HWP) {
                #pragma unroll
                for (int rr = 0; rr < 2; rr++) {
                    const int mm = mA + rr * 8;
                    float v0 = acc[mt][nt][rr * 2 + 0] + (rr ? biasB : biasA);
                    float v1 = acc[mt][nt][rr * 2 + 1] + (rr ? biasB : biasA);
                    if (MODE == 1) { v0 = gelu_tanh_f(v0); v1 = gelu_tanh_f(v1); }
                    const size_t o = ((size_t)b * M + mm) * HWP + n;
                    if (MODE == 2) {
                        float2 r2 = *reinterpret_cast<const float2*>(&resid[o]);
                        v0 += r2.x; v1 += r2.y;
                    }
                    *reinterpret_cast<float2*>(&out[o]) = make_float2(v0, v1);
                    if (MODE == 0) {
                        s1 += (double)v0 + (double)v1;
                        s2 += (double)v0 * v0 + (double)v1 * v1;
                    }
                }
            }
        }
    }

    if (MODE == 0) {
        #pragma unroll
        for (int off = 16; off > 0; off >>= 1) {
            s1 += __shfl_down_sync(0xffffffff, s1, off);
            s2 += __shfl_down_sync(0xffffffff, s2, off);
        }
        if (lane == 0) { s_red[warp] = s1; s_red[8 + warp] = s2; }
        __syncthreads();
        if (warp == 0) {
            double a1 = (lane < 8) ? s_red[lane] : 0.0;
            double a2 = (lane < 8) ? s_red[8 + lane] : 0.0;
            #pragma unroll
            for (int off = 4; off > 0; off >>= 1) {
                a1 += __shfl_down_sync(0xffffffff, a1, off);
                a2 += __shfl_down_sync(0xffffffff, a2, off);
            }
            if (lane == 0) {
                atomicAdd(&g_red[b * 2 + 0], a1);
                atomicAdd(&g_red[b * 2 + 1], a2);
            }
        }
    }
}

// ---------------- LayerNorm apply (stats from g_red) ----------------
// grid: (CHW/4/256 = 294, B), block 256
__global__ void ln_apply_kernel(const float* __restrict__ ln_w,
                                const float* __restrict__ ln_b) {
    __shared__ float s_mu, s_rs;
    const int b = blockIdx.y;
    if (threadIdx.x == 0) {
        double mu  = g_red[b * 2 + 0] / (double)CHW;
        double var = g_red[b * 2 + 1] / (double)CHW - mu * mu;
        s_mu = (float)mu;
        s_rs = (float)(1.0 / sqrt(var + 1e-6));
    }
    __syncthreads();
    const int i = (blockIdx.x * 256 + threadIdx.x) * 4;
    const float mu = s_mu, rs = s_rs;
    float4 v = *reinterpret_cast<const float4*>(&g_buf2[(size_t)b * CHW + i]);
    float4 w = *reinterpret_cast<const float4*>(&ln_w[i]);
    float4 bb = *reinterpret_cast<const float4*>(&ln_b[i]);
    v.x = fmaf((v.x - mu) * rs, w.x, bb.x);
    v.y = fmaf((v.y - mu) * rs, w.y, bb.y);
    v.z = fmaf((v.z - mu) * rs, w.z, bb.z);
    v.w = fmaf((v.w - mu) * rs, w.w, bb.w);
    *reinterpret_cast<float4*>(&g_buf1[(size_t)b * CHW + i]) = v;
}

// ---------------- power iteration: top singular value per (b,c4) slice ----------------
// grid: B*C4 = 6144, block: 64
__global__ void power_iter_kernel() {
    __shared__ float sA[56 * 57];
    __shared__ float sv[56], su[56], sz[56];
    __shared__ float s_nrm;

    const int bc = blockIdx.x;
    const int t  = threadIdx.x;
    const float* src = g_buf3 + (size_t)bc * HWP;

    for (int i = t; i < HWP; i += 64) {
        int r = i / 56, c = i - r * 56;
        sA[r * 57 + c] = src[i];
    }
    if (t < 56) sv[t] = 0.1336306f;
    __syncthreads();

    float nz = 0.0f;
    const int ITER = 12;
    for (int it = 0; it < ITER; it++) {
        if (t < 56) {
            float s = 0.0f;
            #pragma unroll 8
            for (int j = 0; j < 56; j++) s = fmaf(sA[t * 57 + j], sv[j], s);
            su[t] = s;
        }
        __syncthreads();
        if (t < 56) {
            float s = 0.0f;
            #pragma unroll 8
            for (int i = 0; i < 56; i++) s = fmaf(sA[i * 57 + t], su[i], s);
            sz[t] = s;
        }
        __syncthreads();
        if (t < 32) {
            float p = sz[t] * sz[t] + ((t + 32) < 56 ? sz[t + 32] * sz[t + 32] : 0.0f);
            #pragma unroll
            for (int off = 16; off > 0; off >>= 1)
                p += __shfl_xor_sync(0xffffffff, p, off);
            if (t == 0) s_nrm = sqrtf(p);
        }
        __syncthreads();
        nz = s_nrm;
        if (t < 56) sv[t] = (nz > 0.0f) ? sz[t] / nz : 0.1336306f;
        __syncthreads();
    }
    if (t == 0) {
        float sigma = sqrtf(nz);
        g_sv[bc] = sigma;
        atomicAdd(&g_svsum, sigma);
    }
}

// ---------------- launch ----------------
extern "C" void kernel_launch(void* const* d_in, const int* in_sizes, int n_in,
                              void* d_out, int out_size) {
    const float* x     = (const float*)d_in[0];
    const float* dw_w  = (const float*)d_in[1];
    const float* dw_b  = (const float*)d_in[2];
    const float* pw_w  = (const float*)d_in[3];
    const float* pw_b  = (const float*)d_in[4];
    const float* ln_w  = (const float*)d_in[5];
    const float* ln_b  = (const float*)d_in[6];
    const float* l1_w  = (const float*)d_in[7];
    const float* l1_b  = (const float*)d_in[8];
    const float* gamma = (const float*)d_in[9];
    const float* beta  = (const float*)d_in[10];
    const float* l2_w  = (const float*)d_in[11];
    const float* l2_b  = (const float*)d_in[12];
    float* out = (float*)d_out;

    float* buf1; cudaGetSymbolAddress((void**)&buf1, g_buf1);
    float* buf2; cudaGetSymbolAddress((void**)&buf2, g_buf2);
    float* buf3; cudaGetSymbolAddress((void**)&buf3, g_buf3);

    const int NB = (HWP + 127) / 128;   // 25

    // 1) depthwise conv -> buf1 (+ zero-init of reductions)
    dw_conv_kernel<<<dim3(1, 7, BB * CC), dim3(56, 8)>>>(x, dw_w, dw_b);

    // 2) pointwise 96->96 -> buf2 (+ fused LN stats)
    gemm_tc<0><<<dim3(NB, 1, BB), 256>>>(pw_w, pw_b, buf1, buf2, CC, CC,
                                         nullptr, nullptr, nullptr);

    // 3) LN apply -> buf1
    ln_apply_kernel<<<dim3(CHW / 4 / 256, BB), 256>>>(ln_w, ln_b);

    // 4) expand 96->384 + GELU -> buf3
    gemm_tc<1><<<dim3(NB, C4 / 96, BB), 256>>>(l1_w, l1_b, buf1, buf3, C4, CC,
                                               nullptr, nullptr, nullptr);

    // 5) top singular value per slice (+ fused sv sum)
    power_iter_kernel<<<BB * C4, 64>>>();

    // 6) GRN affine + project 384->96 + bias + residual -> out
    gemm_tc<2><<<dim3(NB, 1, BB), 256>>>(l2_w, l2_b, buf3, out, CC, C4,
                                         gamma, beta, x);
}

// round 4
// speedup vs baseline: 2.0019x; 1.1474x over previous
#include <cuda_runtime.h>
#include <math.h>

#define BB   16
#define CC   96
#define C4   384
#define HH   56
#define WW   56
#define HWP  3136          // 56*56
#define CHW  301056        // 96*3136

// ---------------- scratch (device globals; no allocation) ----------------
__device__ float  g_buf1[BB * CC * HWP];   // dw out
__device__ float  g_buf2[BB * CC * HWP];   // pw out (pre-LN)
__device__ float  g_buf3[BB * C4 * HWP];   // expand+gelu out
__device__ double g_red[BB * 2];           // LN sum / sumsq per batch
__device__ float  g_sv[BB * C4];           // top singular values
__device__ float  g_svsum;                 // sum of all sv

// ---------------- helpers ----------------
__device__ __forceinline__ float gelu_tanh_f(float x) {
    const float c = 0.7978845608028654f;
    float x3 = x * x * x;
    return 0.5f * x * (1.0f + tanhf(c * (x + 0.044715f * x3)));
}

__device__ __forceinline__ float tf32r(float x) {
    unsigned u;
    asm("cvt.rna.tf32.f32 %0, %1;" : "=r"(u) : "f"(x));
    return __uint_as_float(u);
}

__device__ __forceinline__ void mma_tf32(float* c, const unsigned* a, const unsigned* b2) {
    asm volatile("mma.sync.aligned.m16n8k8.row.col.f32.tf32.tf32.f32 "
        "{%0,%1,%2,%3}, {%4,%5,%6,%7}, {%8,%9}, {%0,%1,%2,%3};"
        : "+f"(c[0]), "+f"(c[1]), "+f"(c[2]), "+f"(c[3])
        : "r"(a[0]), "r"(a[1]), "r"(a[2]), "r"(a[3]), "r"(b2[0]), "r"(b2[1]));
}

// ---------------- 1) depthwise 7x7 conv + bias (+ scratch zero-init) ----------------
__global__ void dw_conv_kernel(const float* __restrict__ x,
                               const float* __restrict__ dw_w,
                               const float* __restrict__ dw_b) {
    __shared__ float tile[14][62];
    __shared__ float sw[49];

    const int bc = blockIdx.z;
    const int c  = bc % CC;
    const int y0 = blockIdx.y * 8;
    const int tx = threadIdx.x;
    const int ty = threadIdx.y;
    const int tid = ty * 56 + tx;

    if (bc == 0 && blockIdx.y == 0) {
        if (tid < BB * 2) g_red[tid] = 0.0;
        if (tid == BB * 2) g_svsum = 0.0f;
    }

    const float* src = x + (size_t)bc * HWP;
    if (tid < 49) sw[tid] = dw_w[c * 49 + tid];

    for (int i = tid; i < 14 * 62; i += 448) {
        int r  = i / 62;
        int cx = i - r * 62;
        int gy = y0 - 3 + r;
        int gx = cx - 3;
        float v = 0.0f;
        if (gy >= 0 && gy < HH && gx >= 0 && gx < WW) v = src[gy * WW + gx];
        tile[r][cx] = v;
    }
    __syncthreads();

    float acc = dw_b[c];
    #pragma unroll
    for (int dy = 0; dy < 7; dy++)
        #pragma unroll
        for (int dx = 0; dx < 7; dx++)
            acc = fmaf(sw[dy * 7 + dx], tile[ty + dy][tx + dx], acc);

    g_buf1[(size_t)bc * HWP + (y0 + ty) * WW + tx] = acc;
}

// ---------------- TF32 tensor-core channel GEMM, fragment-order smem ----------------
// out[b,m,n] = sum_k W[m,k]*in[b,k,n]
// MODE 0: +bias, fused LN sum/sumsq reduction             (pointwise)
// MODE 1: LN applied to B at staging, +bias, gelu          (expand)
// MODE 2: B scaled by GRN affine, +bias, +residual         (project)
// grid: (ceil(HW/128), M/96, B), block: 256 (8 warps = 2m x 4n)
template <int MODE>
__global__ __launch_bounds__(256)
void gemm_tc(const float* __restrict__ W,
             const float* __restrict__ bias,
             const float* __restrict__ in,
             float* __restrict__ out,
             int M, int K,
             const float* __restrict__ p0,   // MODE1: ln_w, MODE2: gamma
             const float* __restrict__ p1,   // MODE1: ln_b, MODE2: beta
             const float* __restrict__ resid) {
    // fragment-order tiles, lane dim padded to 33 to break STS conflicts
    __shared__ float Af[4][6][33][4];    // [kstep][mtile][lane][reg]
    __shared__ float Bf[4][16][33][2];   // [kstep][ntile][lane][reg]
    __shared__ double s_red[16];

    const int n0 = blockIdx.x * 128;
    const int m0 = blockIdx.y * 96;
    const int b  = blockIdx.z;
    const int tid  = threadIdx.x;
    const int lane = tid & 31;
    const int warp = tid >> 5;
    const int warp_m = warp >> 2;    // 0..1
    const int warp_n = warp & 3;     // 0..3

    const float* inb = in + (size_t)b * K * HWP;
    const float inv_sum = (MODE == 2) ? (1.0f / g_svsum) : 0.0f;

    float mu = 0.0f, rs = 0.0f;
    if (MODE == 1) {
        double m_ = g_red[b * 2 + 0] / (double)CHW;
        double v_ = g_red[b * 2 + 1] / (double)CHW - m_ * m_;
        mu = (float)m_;
        rs = (float)(1.0 / sqrt(v_ + 1e-6));
    }

    float acc[3][4][4];
    #pragma unroll
    for (int mt = 0; mt < 3; mt++)
        #pragma unroll
        for (int nt = 0; nt < 4; nt++)
            #pragma unroll
            for (int j = 0; j < 4; j++) acc[mt][nt][j] = 0.0f;

    const int NK = K >> 5;
    float4 rA[3], rB[4];

    // ---- load tile k0 into registers ----
    auto load_tile = [&](int k0) {
        #pragma unroll
        for (int u = 0; u < 3; u++) {
            int i = tid + u * 256;
            int m = i >> 3, q = i & 7;
            rA[u] = *reinterpret_cast<const float4*>(&W[(size_t)(m0 + m) * K + k0 + q * 4]);
        }
        #pragma unroll
        for (int u = 0; u < 4; u++) {
            int i = tid + u * 256;
            int kk = i >> 5, nq = i & 31;
            int gn = n0 + nq * 4;
            rB[u] = (gn < HWP)
                  ? *reinterpret_cast<const float4*>(&inb[(size_t)(k0 + kk) * HWP + gn])
                  : make_float4(0.f, 0.f, 0.f, 0.f);
        }
    };

    // ---- store registers into fragment-order smem (with cvt + transforms) ----
    auto store_tile = [&](int k0) {
        #pragma unroll
        for (int u = 0; u < 3; u++) {
            int i = tid + u * 256;
            int m = i >> 3, q = i & 7;
            int ks = q >> 1;
            int mt = m >> 4;
            int g  = m & 7;
            int rp = ((q & 1) << 1) | ((m >> 3) & 1);
            float* dst = &Af[ks][mt][g * 4][rp];
            dst[0]  = tf32r(rA[u].x);
            dst[4]  = tf32r(rA[u].y);
            dst[8]  = tf32r(rA[u].z);
            dst[12] = tf32r(rA[u].w);
        }
        #pragma unroll
        for (int u = 0; u < 4; u++) {
            int i = tid + u * 256;
            int kk = i >> 5, nq = i & 31;
            int gn = n0 + nq * 4;
            float4 v = rB[u];
            if (MODE == 1) {
                if (gn < HWP) {
                    size_t li = (size_t)(k0 + kk) * HWP + gn;
                    float4 lw = *reinterpret_cast<const float4*>(&p0[li]);
                    float4 lb = *reinterpret_cast<const float4*>(&p1[li]);
                    v.x = fmaf((v.x - mu) * rs, lw.x, lb.x);
                    v.y = fmaf((v.y - mu) * rs, lw.y, lb.y);
                    v.z = fmaf((v.z - mu) * rs, lw.z, lb.z);
                    v.w = fmaf((v.w - mu) * rs, lw.w, lb.w);
                }
            }
            if (MODE == 2) {
                int idx = b * C4 + k0 + kk;
                float s  = fmaf(p0[idx] * g_sv[idx], inv_sum, 1.0f);
                float sh = p1[idx];
                v.x = fmaf(v.x, s, sh);
                v.y = fmaf(v.y, s, sh);
                v.z = fmaf(v.z, s, sh);
                v.w = fmaf(v.w, s, sh);
            }
            int ks  = kk >> 3, kin = kk & 7;
            int nt  = nq >> 1;
            float* dst = &Bf[ks][nt][((nq & 1) << 4) + (kin & 3)][kin >> 2];
            dst[0]  = tf32r(v.x);
            dst[8]  = tf32r(v.y);
            dst[16] = tf32r(v.z);
            dst[24] = tf32r(v.w);
        }
    };

    load_tile(0);
    for (int it = 0; it < NK; it++) {
        store_tile(it << 5);
        __syncthreads();
        if (it + 1 < NK) load_tile((it + 1) << 5);

        #pragma unroll
        for (int ks = 0; ks < 4; ks++) {
            float4 afr[3];
            #pragma unroll
            for (int mt = 0; mt < 3; mt++)
                afr[mt] = *reinterpret_cast<const float4*>(&Af[ks][warp_m * 3 + mt][lane][0]);
            float2 bfr[4];
            #pragma unroll
            for (int nt = 0; nt < 4; nt++)
                bfr[nt] = *reinterpret_cast<const float2*>(&Bf[ks][warp_n * 4 + nt][lane][0]);
            #pragma unroll
            for (int mt = 0; mt < 3; mt++)
                #pragma unroll
                for (int nt = 0; nt < 4; nt++)
                    mma_tf32(acc[mt][nt],
                             reinterpret_cast<const unsigned*>(&afr[mt]),
                             reinterpret_cast<const unsigned*>(&bfr[nt]));
        }
        __syncthreads();
    }

    // ---- epilogue ----
    double s1 = 0.0, s2 = 0.0;
    #pragma unroll
    for (int mt = 0; mt < 3; mt++) {
        const int mA = m0 + warp_m * 48 + mt * 16 + (lane >> 2);
        const float biasA = bias[mA];
        const float biasB = bias[mA + 8];
        #pragma unroll
        for (int nt = 0; nt < 4; nt++) {
            const int n = n0 + warp_n * 32 + nt * 8 + 2 * (lane & 3);
            if (n < HWP) {
                #pragma unroll
                for (int rr = 0; rr < 2; rr++) {
                    const int mm = mA + rr * 8;
                    float v0 = acc[mt][nt][rr * 2 + 0] + (rr ? biasB : biasA);
                    float v1 = acc[mt][nt][rr * 2 + 1] + (rr ? biasB : biasA);
                    if (MODE == 1) { v0 = gelu_tanh_f(v0); v1 = gelu_tanh_f(v1); }
                    const size_t o = ((size_t)b * M + mm) * HWP + n;
                    if (MODE == 2) {
                        float2 r2 = *reinterpret_cast<const float2*>(&resid[o]);
                        v0 += r2.x; v1 += r2.y;
                    }
                    *reinterpret_cast<float2*>(&out[o]) = make_float2(v0, v1);
                    if (MODE == 0) {
                        s1 += (double)v0 + (double)v1;
                        s2 += (double)v0 * v0 + (double)v1 * v1;
                    }
                }
            }
        }
    }

    if (MODE == 0) {
        #pragma unroll
        for (int off = 16; off > 0; off >>= 1) {
            s1 += __shfl_down_sync(0xffffffff, s1, off);
            s2 += __shfl_down_sync(0xffffffff, s2, off);
        }
        if (lane == 0) { s_red[warp] = s1; s_red[8 + warp] = s2; }
        __syncthreads();
        if (warp == 0) {
            double a1 = (lane < 8) ? s_red[lane] : 0.0;
            double a2 = (lane < 8) ? s_red[8 + lane] : 0.0;
            #pragma unroll
            for (int off = 4; off > 0; off >>= 1) {
                a1 += __shfl_down_sync(0xffffffff, a1, off);
                a2 += __shfl_down_sync(0xffffffff, a2, off);
            }
            if (lane == 0) {
                atomicAdd(&g_red[b * 2 + 0], a1);
                atomicAdd(&g_red[b * 2 + 1], a2);
            }
        }
    }
}

// ---------------- power iteration: top singular value per (b,c4) slice ----------------
// grid: B*C4 = 6144, block: 128
__global__ void power_iter_kernel() {
    __shared__ float sA[56 * 57];
    __shared__ float sv[56], su[56];
    __shared__ float s_nrm;

    const int bc = blockIdx.x;
    const int t  = threadIdx.x;
    const float* src = g_buf3 + (size_t)bc * HWP;

    for (int i = t; i < HWP; i += 128) {
        int r = i / 56, c = i - r * 56;
        sA[r * 57 + c] = src[i];
    }
    if (t < 56) sv[t] = 0.1336306f;   // 1/sqrt(56)
    __syncthreads();

    const int rr = (t >> 1) % 56;     // row/col (threads >=112 duplicate, discarded)
    const int h  = t & 1;             // half: 28 terms each
    const bool valid = (t >> 1) < 56;

    float nz = 0.0f;
    const int ITER = 6;
    for (int it = 0; it < ITER; it++) {
        // u = A v
        {
            float s = 0.0f;
            const float* row = &sA[rr * 57 + h * 28];
            const float* vv  = &sv[h * 28];
            #pragma unroll
            for (int j = 0; j < 28; j++) s = fmaf(row[j], vv[j], s);
            s += __shfl_xor_sync(0xffffffff, s, 1);
            if (h == 0 && valid) su[rr] = s;
        }
        __syncthreads();
        // z = A^T u  -> store into sv
        {
            float s = 0.0f;
            #pragma unroll
            for (int j = 0; j < 28; j++) s = fmaf(sA[(h * 28 + j) * 57 + rr], su[h * 28 + j], s);
            s += __shfl_xor_sync(0xffffffff, s, 1);
            if (h == 0 && valid) sv[rr] = s;
        }
        __syncthreads();
        if (t < 32) {
            float p = sv[t] * sv[t] + ((t < 24) ? sv[t + 32] * sv[t + 32] : 0.0f);
            #pragma unroll
            for (int off = 16; off > 0; off >>= 1)
                p += __shfl_xor_sync(0xffffffff, p, off);
            if (t == 0) s_nrm = sqrtf(p);
        }
        __syncthreads();
        nz = s_nrm;
        if (t < 56) sv[t] = (nz > 0.0f) ? sv[t] / nz : 0.1336306f;
        __syncthreads();
    }
    if (t == 0) {
        float sigma = sqrtf(nz);
        g_sv[bc] = sigma;
        atomicAdd(&g_svsum, sigma);
    }
}

// ---------------- launch ----------------
extern "C" void kernel_launch(void* const* d_in, const int* in_sizes, int n_in,
                              void* d_out, int out_size) {
    const float* x     = (const float*)d_in[0];
    const float* dw_w  = (const float*)d_in[1];
    const float* dw_b  = (const float*)d_in[2];
    const float* pw_w  = (const float*)d_in[3];
    const float* pw_b  = (const float*)d_in[4];
    const float* ln_w  = (const float*)d_in[5];
    const float* ln_b  = (const float*)d_in[6];
    const float* l1_w  = (const float*)d_in[7];
    const float* l1_b  = (const float*)d_in[8];
    const float* gamma = (const float*)d_in[9];
    const float* beta  = (const float*)d_in[10];
    const float* l2_w  = (const float*)d_in[11];
    const float* l2_b  = (const float*)d_in[12];
    float* out = (float*)d_out;

    float* buf1; cudaGetSymbolAddress((void**)&buf1, g_buf1);
    float* buf2; cudaGetSymbolAddress((void**)&buf2, g_buf2);
    float* buf3; cudaGetSymbolAddress((void**)&buf3, g_buf3);

    const int NB = (HWP + 127) / 128;   // 25

    // 1) depthwise conv -> buf1 (+ zero-init of reductions)
    dw_conv_kernel<<<dim3(1, 7, BB * CC), dim3(56, 8)>>>(x, dw_w, dw_b);

    // 2) pointwise 96->96 -> buf2 (+ fused LN stats)
    gemm_tc<0><<<dim3(NB, 1, BB), 256>>>(pw_w, pw_b, buf1, buf2, CC, CC,
                                         nullptr, nullptr, nullptr);

    // 3) expand 96->384 with fused LN on input + GELU -> buf3
    gemm_tc<1><<<dim3(NB, C4 / 96, BB), 256>>>(l1_w, l1_b, buf2, buf3, C4, CC,
                                               ln_w, ln_b, nullptr);

    // 4) top singular value per slice (+ fused sv sum)
    power_iter_kernel<<<BB * C4, 128>>>();

    // 5) GRN affine + project 384->96 + bias + residual -> out
    gemm_tc<2><<<dim3(NB, 1, BB), 256>>>(l2_w, l2_b, buf3, out, CC, C4,
                                         gamma, beta, x);
}

// round 6
// speedup vs baseline: 2.0123x; 1.0052x over previous
#include <cuda_runtime.h>
#include <math.h>

#define BB   16
#define CC   96
#define C4   384
#define HH   56
#define WW   56
#define HWP  3136          // 56*56
#define CHW  301056        // 96*3136

// ---------------- scratch (device globals; no allocation) ----------------
__device__ float  g_buf1[BB * CC * HWP];   // dw out
__device__ float  g_buf2[BB * CC * HWP];   // pw out (pre-LN)
__device__ float  g_buf3[BB * C4 * HWP];   // expand+gelu out
__device__ double g_red[BB * 2];           // LN sum / sumsq per batch
__device__ float  g_sv[BB * C4];           // top singular values
__device__ float  g_svsum;                 // sum of all sv

// ---------------- helpers ----------------
__device__ __forceinline__ float gelu_tanh_f(float x) {
    const float c = 0.7978845608028654f;
    float x3 = x * x * x;
    return 0.5f * x * (1.0f + tanhf(c * (x + 0.044715f * x3)));
}

__device__ __forceinline__ float tf32r(float x) {
    unsigned u;
    asm("cvt.rna.tf32.f32 %0, %1;" : "=r"(u) : "f"(x));
    return __uint_as_float(u);
}

__device__ __forceinline__ void mma_tf32(float* c, const unsigned* a, const unsigned* b2) {
    asm volatile("mma.sync.aligned.m16n8k8.row.col.f32.tf32.tf32.f32 "
        "{%0,%1,%2,%3}, {%4,%5,%6,%7}, {%8,%9}, {%0,%1,%2,%3};"
        : "+f"(c[0]), "+f"(c[1]), "+f"(c[2]), "+f"(c[3])
        : "r"(a[0]), "r"(a[1]), "r"(a[2]), "r"(a[3]), "r"(b2[0]), "r"(b2[1]));
}

// ---------------- 1) depthwise 7x7 conv + bias (+ scratch zero-init) ----------------
__global__ void dw_conv_kernel(const float* __restrict__ x,
                               const float* __restrict__ dw_w,
                               const float* __restrict__ dw_b) {
    __shared__ float tile[14][62];
    __shared__ float sw[49];

    const int bc = blockIdx.z;
    const int c  = bc % CC;
    const int y0 = blockIdx.y * 8;
    const int tx = threadIdx.x;
    const int ty = threadIdx.y;
    const int tid = ty * 56 + tx;

    if (bc == 0 && blockIdx.y == 0) {
        if (tid < BB * 2) g_red[tid] = 0.0;
        if (tid == BB * 2) g_svsum = 0.0f;
    }

    const float* src = x + (size_t)bc * HWP;
    if (tid < 49) sw[tid] = dw_w[c * 49 + tid];

    for (int i = tid; i < 14 * 62; i += 448) {
        int r  = i / 62;
        int cx = i - r * 62;
        int gy = y0 - 3 + r;
        int gx = cx - 3;
        float v = 0.0f;
        if (gy >= 0 && gy < HH && gx >= 0 && gx < WW) v = src[gy * WW + gx];
        tile[r][cx] = v;
    }
    __syncthreads();

    float acc = dw_b[c];
    #pragma unroll
    for (int dy = 0; dy < 7; dy++)
        #pragma unroll
        for (int dx = 0; dx < 7; dx++)
            acc = fmaf(sw[dy * 7 + dx], tile[ty + dy][tx + dx], acc);

    g_buf1[(size_t)bc * HWP + (y0 + ty) * WW + tx] = acc;
}

// ---------------- TF32 tensor-core channel GEMM, fragment-order smem, BN=64 ----------------
// out[b,m,n] = sum_k W[m,k]*in[b,k,n]
// MODE 0: +bias, fused LN sum/sumsq reduction             (pointwise)
// MODE 1: LN applied to B at staging, +bias, gelu          (expand)
// MODE 2: B scaled by GRN affine, +bias, +residual         (project)
// grid: (HW/64, M/96, B), block: 256 (8 warps = 2m x 4n; warp tile 48x16)
template <int MODE>
__global__ __launch_bounds__(256)
void gemm_tc(const float* __restrict__ W,
             const float* __restrict__ bias,
             const float* __restrict__ in,
             float* __restrict__ out,
             int M, int K,
             const float* __restrict__ p0,   // MODE1: ln_w, MODE2: gamma
             const float* __restrict__ p1,   // MODE1: ln_b, MODE2: beta
             const float* __restrict__ resid) {
    // fragment-order tiles, lane dim padded to 33 to break STS conflicts
    __shared__ float Af[4][6][33][4];    // [kstep][mtile][lane][reg]
    __shared__ float Bf[4][8][33][2];    // [kstep][ntile][lane][reg]
    __shared__ double s_red[16];

    const int n0 = blockIdx.x * 64;
    const int m0 = blockIdx.y * 96;
    const int b  = blockIdx.z;
    const int tid  = threadIdx.x;
    const int lane = tid & 31;
    const int warp = tid >> 5;
    const int warp_m = warp >> 2;    // 0..1
    const int warp_n = warp & 3;     // 0..3

    const float* inb = in + (size_t)b * K * HWP;
    const float inv_sum = (MODE == 2) ? (1.0f / g_svsum) : 0.0f;

    float mu = 0.0f, rs = 0.0f;
    if (MODE == 1) {
        double m_ = g_red[b * 2 + 0] / (double)CHW;
        double v_ = g_red[b * 2 + 1] / (double)CHW - m_ * m_;
        mu = (float)m_;
        rs = (float)(1.0 / sqrt(v_ + 1e-6));
    }

    float acc[3][2][4];
    #pragma unroll
    for (int mt = 0; mt < 3; mt++)
        #pragma unroll
        for (int nt = 0; nt < 2; nt++)
            #pragma unroll
            for (int j = 0; j < 4; j++) acc[mt][nt][j] = 0.0f;

    const int NK = K >> 5;
    float4 rA[3], rB[2];

    // ---- load tile k0 into registers ----
    auto load_tile = [&](int k0) {
        #pragma unroll
        for (int u = 0; u < 3; u++) {
            int i = tid + u * 256;
            int m = i >> 3, q = i & 7;
            rA[u] = *reinterpret_cast<const float4*>(&W[(size_t)(m0 + m) * K + k0 + q * 4]);
        }
        #pragma unroll
        for (int u = 0; u < 2; u++) {
            int i = tid + u * 256;
            int kk = i >> 4, nq = i & 15;
            rB[u] = *reinterpret_cast<const float4*>(&inb[(size_t)(k0 + kk) * HWP + n0 + nq * 4]);
        }
    };

    // ---- store registers into fragment-order smem (with cvt + transforms) ----
    auto store_tile = [&](int k0) {
        #pragma unroll
        for (int u = 0; u < 3; u++) {
            int i = tid + u * 256;
            int m = i >> 3, q = i & 7;
            int ks = q >> 1;
            int mt = m >> 4;
            int g  = m & 7;
            int rp = ((q & 1) << 1) | ((m >> 3) & 1);
            float* dst = &Af[ks][mt][g * 4][rp];
            dst[0]  = tf32r(rA[u].x);
            dst[4]  = tf32r(rA[u].y);
            dst[8]  = tf32r(rA[u].z);
            dst[12] = tf32r(rA[u].w);
        }
        #pragma unroll
        for (int u = 0; u < 2; u++) {
            int i = tid + u * 256;
            int kk = i >> 4, nq = i & 15;
            float4 v = rB[u];
            if (MODE == 1) {
                size_t li = (size_t)(k0 + kk) * HWP + n0 + nq * 4;
                float4 lw = *reinterpret_cast<const float4*>(&p0[li]);
                float4 lb = *reinterpret_cast<const float4*>(&p1[li]);
                v.x = fmaf((v.x - mu) * rs, lw.x, lb.x);
                v.y = fmaf((v.y - mu) * rs, lw.y, lb.y);
                v.z = fmaf((v.z - mu) * rs, lw.z, lb.z);
                v.w = fmaf((v.w - mu) * rs, lw.w, lb.w);
            }
            if (MODE == 2) {
                int idx = b * C4 + k0 + kk;
                float s  = fmaf(p0[idx] * g_sv[idx], inv_sum, 1.0f);
                float sh = p1[idx];
                v.x = fmaf(v.x, s, sh);
                v.y = fmaf(v.y, s, sh);
                v.z = fmaf(v.z, s, sh);
                v.w = fmaf(v.w, s, sh);
            }
            int ks  = kk >> 3, kin = kk & 7;
            int nt  = nq >> 1;
            float* dst = &Bf[ks][nt][((nq & 1) << 4) + (kin & 3)][kin >> 2];
            dst[0]  = tf32r(v.x);
            dst[8]  = tf32r(v.y);
            dst[16] = tf32r(v.z);
            dst[24] = tf32r(v.w);
        }
    };

    load_tile(0);
    for (int it = 0; it < NK; it++) {
        store_tile(it << 5);
        __syncthreads();
        if (it + 1 < NK) load_tile((it + 1) << 5);

        #pragma unroll
        for (int ks = 0; ks < 4; ks++) {
            float4 afr[3];
            #pragma unroll
            for (int mt = 0; mt < 3; mt++)
                afr[mt] = *reinterpret_cast<const float4*>(&Af[ks][warp_m * 3 + mt][lane][0]);
            float2 bfr[2];
            #pragma unroll
            for (int nt = 0; nt < 2; nt++)
                bfr[nt] = *reinterpret_cast<const float2*>(&Bf[ks][warp_n * 2 + nt][lane][0]);
            #pragma unroll
            for (int mt = 0; mt < 3; mt++)
                #pragma unroll
                for (int nt = 0; nt < 2; nt++)
                    mma_tf32(acc[mt][nt],
                             reinterpret_cast<const unsigned*>(&afr[mt]),
                             reinterpret_cast<const unsigned*>(&bfr[nt]));
        }
        __syncthreads();
    }

    // ---- epilogue ----
    double s1 = 0.0, s2 = 0.0;
    #pragma unroll
    for (int mt = 0; mt < 3; mt++) {
        const int mA = m0 + warp_m * 48 + mt * 16 + (lane >> 2);
        const float biasA = bias[mA];
        const float biasB = bias[mA + 8];
        #pragma unroll
        for (int nt = 0; nt < 2; nt++) {
            const int n = n0 + warp_n * 16 + nt * 8 + 2 * (lane & 3);
            #pragma unroll
            for (int rr = 0; rr < 2; rr++) {
                const int mm = mA + rr * 8;
                float v0 = acc[mt][nt][rr * 2 + 0] + (rr ? biasB : biasA);
                float v1 = acc[mt][nt][rr * 2 + 1] + (rr ? biasB : biasA);
                if (MODE == 1) { v0 = gelu_tanh_f(v0); v1 = gelu_tanh_f(v1); }
                const size_t o = ((size_t)b * M + mm) * HWP + n;
                if (MODE == 2) {
                    float2 r2 = *reinterpret_cast<const float2*>(&resid[o]);
                    v0 += r2.x; v1 += r2.y;
                }
                *reinterpret_cast<float2*>(&out[o]) = make_float2(v0, v1);
                if (MODE == 0) {
                    s1 += (double)v0 + (double)v1;
                    s2 += (double)v0 * v0 + (double)v1 * v1;
                }
            }
        }
    }

    if (MODE == 0) {
        #pragma unroll
        for (int off = 16; off > 0; off >>= 1) {
            s1 += __shfl_down_sync(0xffffffff, s1, off);
            s2 += __shfl_down_sync(0xffffffff, s2, off);
        }
        if (lane == 0) { s_red[warp] = s1; s_red[8 + warp] = s2; }
        __syncthreads();
        if (warp == 0) {
            double a1 = (lane < 8) ? s_red[lane] : 0.0;
            double a2 = (lane < 8) ? s_red[8 + lane] : 0.0;
            #pragma unroll
            for (int off = 4; off > 0; off >>= 1) {
                a1 += __shfl_down_sync(0xffffffff, a1, off);
                a2 += __shfl_down_sync(0xffffffff, a2, off);
            }
            if (lane == 0) {
                atomicAdd(&g_red[b * 2 + 0], a1);
                atomicAdd(&g_red[b * 2 + 1], a2);
            }
        }
    }
}

// ---------------- power iteration v2: A and A^T in smem, float4 rows ----------------
// grid: B*C4 = 6144, block: 128
// NOTE: all shuffles executed by ALL threads (no divergent exit); invalid
// threads (t>=112) compute on clamped row 0 and never store.
__global__ void power_iter_kernel() {
    __shared__ float sA [56 * 60];   // row pitch 60 floats (16B-aligned rows)
    __shared__ float sAt[56 * 60];   // transpose
    __shared__ float sv[64], su[64];
    __shared__ float s_nrm;

    const int bc = blockIdx.x;
    const int t  = threadIdx.x;
    const float* src = g_buf3 + (size_t)bc * HWP;

    // load + transpose (4 | 56, each float4 stays within one row)
    for (int i = t * 4; i < HWP; i += 512) {
        float4 v = *reinterpret_cast<const float4*>(src + i);
        int r = i / 56;
        int c = i - r * 56;
        *reinterpret_cast<float4*>(&sA[r * 60 + c]) = v;
        sAt[(c + 0) * 60 + r] = v.x;
        sAt[(c + 1) * 60 + r] = v.y;
        sAt[(c + 2) * 60 + r] = v.z;
        sAt[(c + 3) * 60 + r] = v.w;
    }
    if (t < 64) sv[t] = (t < 56) ? 0.1336306f : 0.0f;   // 1/sqrt(56)
    __syncthreads();

    const int r     = t >> 1;            // logical row 0..63
    const int h     = t & 1;             // half: 28 elements
    const bool valid = (r < 56);
    const int rc    = valid ? r : 0;     // clamped (in-bounds) row for compute

    float nz = 0.0f;
    #pragma unroll
    for (int it = 0; it < 3; it++) {
        // u = A v   (all threads compute; only valid store)
        {
            const float4* row = reinterpret_cast<const float4*>(&sA[rc * 60 + h * 28]);
            const float4* vv  = reinterpret_cast<const float4*>(&sv[h * 28]);
            float s = 0.0f;
            #pragma unroll
            for (int j = 0; j < 7; j++) {
                float4 a4 = row[j], v4 = vv[j];
                s = fmaf(a4.x, v4.x, s); s = fmaf(a4.y, v4.y, s);
                s = fmaf(a4.z, v4.z, s); s = fmaf(a4.w, v4.w, s);
            }
            s += __shfl_xor_sync(0xffffffff, s, 1);
            if (valid && h == 0) su[r] = s;
        }
        __syncthreads();
        // z = A^T u (row-major on sAt) -> overwrite sv
        {
            const float4* row = reinterpret_cast<const float4*>(&sAt[rc * 60 + h * 28]);
            const float4* uu  = reinterpret_cast<const float4*>(&su[h * 28]);
            float s = 0.0f;
            #pragma unroll
            for (int j = 0; j < 7; j++) {
                float4 a4 = row[j], u4 = uu[j];
                s = fmaf(a4.x, u4.x, s); s = fmaf(a4.y, u4.y, s);
                s = fmaf(a4.z, u4.z, s); s = fmaf(a4.w, u4.w, s);
            }
            s += __shfl_xor_sync(0xffffffff, s, 1);
            if (valid && h == 0) sv[r] = s;
        }
        __syncthreads();
        // nz = ||z||, normalize
        if (t < 32) {
            float p = sv[t] * sv[t] + ((t < 24) ? sv[t + 32] * sv[t + 32] : 0.0f);
            #pragma unroll
            for (int off = 16; off > 0; off >>= 1)
                p += __shfl_xor_sync(0xffffffff, p, off);
            if (t == 0) s_nrm = sqrtf(p);
        }
        __syncthreads();
        nz = s_nrm;
        if (t < 56) sv[t] = (nz > 0.0f) ? sv[t] / nz : 0.1336306f;
        __syncthreads();
    }
    if (t == 0) {
        float sigma = sqrtf(nz);   // ||A^T A v|| with unit v -> sigma^2
        g_sv[bc] = sigma;
        atomicAdd(&g_svsum, sigma);
    }
}

// ---------------- launch ----------------
extern "C" void kernel_launch(void* const* d_in, const int* in_sizes, int n_in,
                              void* d_out, int out_size) {
    const float* x     = (const float*)d_in[0];
    const float* dw_w  = (const float*)d_in[1];
    const float* dw_b  = (const float*)d_in[2];
    const float* pw_w  = (const float*)d_in[3];
    const float* pw_b  = (const float*)d_in[4];
    const float* ln_w  = (const float*)d_in[5];
    const float* ln_b  = (const float*)d_in[6];
    const float* l1_w  = (const float*)d_in[7];
    const float* l1_b  = (const float*)d_in[8];
    const float* gamma = (const float*)d_in[9];
    const float* beta  = (const float*)d_in[10];
    const float* l2_w  = (const float*)d_in[11];
    const float* l2_b  = (const float*)d_in[12];
    float* out = (float*)d_out;

    float* buf1; cudaGetSymbolAddress((void**)&buf1, g_buf1);
    float* buf2; cudaGetSymbolAddress((void**)&buf2, g_buf2);
    float* buf3; cudaGetSymbolAddress((void**)&buf3, g_buf3);

    const int NB = HWP / 64;   // 49, exact

    // 1) depthwise conv -> buf1 (+ zero-init of reductions)
    dw_conv_kernel<<<dim3(1, 7, BB * CC), dim3(56, 8)>>>(x, dw_w, dw_b);

    // 2) pointwise 96->96 -> buf2 (+ fused LN stats)
    gemm_tc<0><<<dim3(NB, 1, BB), 256>>>(pw_w, pw_b, buf1, buf2, CC, CC,
                                         nullptr, nullptr, nullptr);

    // 3) expand 96->384 with fused LN on input + GELU -> buf3
    gemm_tc<1><<<dim3(NB, C4 / 96, BB), 256>>>(l1_w, l1_b, buf2, buf3, C4, CC,
                                               ln_w, ln_b, nullptr);

    // 4) top singular value per slice (+ fused sv sum)
    power_iter_kernel<<<BB * C4, 128>>>();

    // 5) GRN affine + project 384->96 + bias + residual -> out
    gemm_tc<2><<<dim3(NB, 1, BB), 256>>>(l2_w, l2_b, buf3, out, CC, C4,
                                         gamma, beta, x);
}

// round 7
// speedup vs baseline: 2.4729x; 1.2289x over previous
#include <cuda_runtime.h>
#include <math.h>

#define BB   16
#define CC   96
#define C4   384
#define HH   56
#define WW   56
#define HWP  3136          // 56*56
#define CHW  301056        // 96*3136

// ---------------- scratch (device globals; no allocation) ----------------
__device__ float  g_buf1[BB * CC * HWP];   // dw out
__device__ float  g_buf2[BB * CC * HWP];   // pw out (pre-LN)
__device__ float  g_buf3[BB * C4 * HWP];   // expand+gelu out
__device__ double g_red[BB * 2];           // LN sum / sumsq per batch
__device__ float  g_sv[BB * C4];           // top singular values
__device__ float  g_svsum;                 // sum of all sv

// ---------------- helpers ----------------
__device__ __forceinline__ float gelu_tanh_f(float x) {
    const float c = 0.7978845608028654f;
    float x3 = x * x * x;
    return 0.5f * x * (1.0f + tanhf(c * (x + 0.044715f * x3)));
}

__device__ __forceinline__ float tf32r(float x) {
    unsigned u;
    asm("cvt.rna.tf32.f32 %0, %1;" : "=r"(u) : "f"(x));
    return __uint_as_float(u);
}

__device__ __forceinline__ void mma_tf32(float* c, const unsigned* a, const unsigned* b2) {
    asm volatile("mma.sync.aligned.m16n8k8.row.col.f32.tf32.tf32.f32 "
        "{%0,%1,%2,%3}, {%4,%5,%6,%7}, {%8,%9}, {%0,%1,%2,%3};"
        : "+f"(c[0]), "+f"(c[1]), "+f"(c[2]), "+f"(c[3])
        : "r"(a[0]), "r"(a[1]), "r"(a[2]), "r"(a[3]), "r"(b2[0]), "r"(b2[1]));
}

// ---------------- 1) depthwise 7x7 conv + bias (+ scratch zero-init) ----------------
__global__ void dw_conv_kernel(const float* __restrict__ x,
                               const float* __restrict__ dw_w,
                               const float* __restrict__ dw_b) {
    __shared__ float tile[14][62];
    __shared__ float sw[49];

    const int bc = blockIdx.z;
    const int c  = bc % CC;
    const int y0 = blockIdx.y * 8;
    const int tx = threadIdx.x;
    const int ty = threadIdx.y;
    const int tid = ty * 56 + tx;

    if (bc == 0 && blockIdx.y == 0) {
        if (tid < BB * 2) g_red[tid] = 0.0;
        if (tid == BB * 2) g_svsum = 0.0f;
    }

    const float* src = x + (size_t)bc * HWP;
    if (tid < 49) sw[tid] = dw_w[c * 49 + tid];

    for (int i = tid; i < 14 * 62; i += 448) {
        int r  = i / 62;
        int cx = i - r * 62;
        int gy = y0 - 3 + r;
        int gx = cx - 3;
        float v = 0.0f;
        if (gy >= 0 && gy < HH && gx >= 0 && gx < WW) v = src[gy * WW + gx];
        tile[r][cx] = v;
    }
    __syncthreads();

    float acc = dw_b[c];
    #pragma unroll
    for (int dy = 0; dy < 7; dy++)
        #pragma unroll
        for (int dx = 0; dx < 7; dx++)
            acc = fmaf(sw[dy * 7 + dx], tile[ty + dy][tx + dx], acc);

    g_buf1[(size_t)bc * HWP + (y0 + ty) * WW + tx] = acc;
}

// ---------------- TF32 tensor-core channel GEMM, fragment-order smem, BN=128 ----------------
// out[b,m,n] = sum_k W[m,k]*in[b,k,n]
// MODE 0: +bias, fused LN sum/sumsq reduction             (pointwise)
// MODE 1: LN applied to B at staging, +bias, gelu          (expand)
// MODE 2: B scaled by GRN affine, +bias, +residual         (project)
// grid: (ceil(HW/128), M/96, B), block: 256 (8 warps = 2m x 4n; warp tile 48x32)
template <int MODE>
__global__ __launch_bounds__(256)
void gemm_tc(const float* __restrict__ W,
             const float* __restrict__ bias,
             const float* __restrict__ in,
             float* __restrict__ out,
             int M, int K,
             const float* __restrict__ p0,   // MODE1: ln_w, MODE2: gamma
             const float* __restrict__ p1,   // MODE1: ln_b, MODE2: beta
             const float* __restrict__ resid) {
    // fragment-order tiles, lane dim padded to 33 to break STS conflicts
    __shared__ float Af[4][6][33][4];    // [kstep][mtile][lane][reg]
    __shared__ float Bf[4][16][33][2];   // [kstep][ntile][lane][reg]
    __shared__ double s_red[16];

    const int n0 = blockIdx.x * 128;
    const int m0 = blockIdx.y * 96;
    const int b  = blockIdx.z;
    const int tid  = threadIdx.x;
    const int lane = tid & 31;
    const int warp = tid >> 5;
    const int warp_m = warp >> 2;    // 0..1
    const int warp_n = warp & 3;     // 0..3

    const float* inb = in + (size_t)b * K * HWP;
    const float inv_sum = (MODE == 2) ? (1.0f / g_svsum) : 0.0f;

    float mu = 0.0f, rs = 0.0f;
    if (MODE == 1) {
        double m_ = g_red[b * 2 + 0] / (double)CHW;
        double v_ = g_red[b * 2 + 1] / (double)CHW - m_ * m_;
        mu = (float)m_;
        rs = (float)(1.0 / sqrt(v_ + 1e-6));
    }

    float acc[3][4][4];
    #pragma unroll
    for (int mt = 0; mt < 3; mt++)
        #pragma unroll
        for (int nt = 0; nt < 4; nt++)
            #pragma unroll
            for (int j = 0; j < 4; j++) acc[mt][nt][j] = 0.0f;

    const int NK = K >> 5;
    float4 rA[3], rB[4];

    // ---- load tile k0 into registers ----
    auto load_tile = [&](int k0) {
        #pragma unroll
        for (int u = 0; u < 3; u++) {
            int i = tid + u * 256;
            int m = i >> 3, q = i & 7;
            rA[u] = *reinterpret_cast<const float4*>(&W[(size_t)(m0 + m) * K + k0 + q * 4]);
        }
        #pragma unroll
        for (int u = 0; u < 4; u++) {
            int i = tid + u * 256;
            int kk = i >> 5, nq = i & 31;
            int gn = n0 + nq * 4;
            rB[u] = (gn < HWP)
                  ? *reinterpret_cast<const float4*>(&inb[(size_t)(k0 + kk) * HWP + gn])
                  : make_float4(0.f, 0.f, 0.f, 0.f);
        }
    };

    // ---- store registers into fragment-order smem (with cvt + transforms) ----
    auto store_tile = [&](int k0) {
        #pragma unroll
        for (int u = 0; u < 3; u++) {
            int i = tid + u * 256;
            int m = i >> 3, q = i & 7;
            int ks = q >> 1;
            int mt = m >> 4;
            int g  = m & 7;
            int rp = ((q & 1) << 1) | ((m >> 3) & 1);
            float* dst = &Af[ks][mt][g * 4][rp];
            dst[0]  = tf32r(rA[u].x);
            dst[4]  = tf32r(rA[u].y);
            dst[8]  = tf32r(rA[u].z);
            dst[12] = tf32r(rA[u].w);
        }
        #pragma unroll
        for (int u = 0; u < 4; u++) {
            int i = tid + u * 256;
            int kk = i >> 5, nq = i & 31;
            int gn = n0 + nq * 4;
            float4 v = rB[u];
            if (MODE == 1) {
                if (gn < HWP) {
                    size_t li = (size_t)(k0 + kk) * HWP + gn;
                    float4 lw = *reinterpret_cast<const float4*>(&p0[li]);
                    float4 lb = *reinterpret_cast<const float4*>(&p1[li]);
                    v.x = fmaf((v.x - mu) * rs, lw.x, lb.x);
                    v.y = fmaf((v.y - mu) * rs, lw.y, lb.y);
                    v.z = fmaf((v.z - mu) * rs, lw.z, lb.z);
                    v.w = fmaf((v.w - mu) * rs, lw.w, lb.w);
                }
            }
            if (MODE == 2) {
                int idx = b * C4 + k0 + kk;
                float s  = fmaf(p0[idx] * g_sv[idx], inv_sum, 1.0f);
                float sh = p1[idx];
                v.x = fmaf(v.x, s, sh);
                v.y = fmaf(v.y, s, sh);
                v.z = fmaf(v.z, s, sh);
                v.w = fmaf(v.w, s, sh);
            }
            int ks  = kk >> 3, kin = kk & 7;
            int nt  = nq >> 1;
            float* dst = &Bf[ks][nt][((nq & 1) << 4) + (kin & 3)][kin >> 2];
            dst[0]  = tf32r(v.x);
            dst[8]  = tf32r(v.y);
            dst[16] = tf32r(v.z);
            dst[24] = tf32r(v.w);
        }
    };

    load_tile(0);
    for (int it = 0; it < NK; it++) {
        store_tile(it << 5);
        __syncthreads();
        if (it + 1 < NK) load_tile((it + 1) << 5);

        #pragma unroll
        for (int ks = 0; ks < 4; ks++) {
            float4 afr[3];
            #pragma unroll
            for (int mt = 0; mt < 3; mt++)
                afr[mt] = *reinterpret_cast<const float4*>(&Af[ks][warp_m * 3 + mt][lane][0]);
            float2 bfr[4];
            #pragma unroll
            for (int nt = 0; nt < 4; nt++)
                bfr[nt] = *reinterpret_cast<const float2*>(&Bf[ks][warp_n * 4 + nt][lane][0]);
            #pragma unroll
            for (int mt = 0; mt < 3; mt++)
                #pragma unroll
                for (int nt = 0; nt < 4; nt++)
                    mma_tf32(acc[mt][nt],
                             reinterpret_cast<const unsigned*>(&afr[mt]),
                             reinterpret_cast<const unsigned*>(&bfr[nt]));
        }
        __syncthreads();
    }

    // ---- epilogue ----
    double s1 = 0.0, s2 = 0.0;
    #pragma unroll
    for (int mt = 0; mt < 3; mt++) {
        const int mA = m0 + warp_m * 48 + mt * 16 + (lane >> 2);
        const float biasA = bias[mA];
        const float biasB = bias[mA + 8];
        #pragma unroll
        for (int nt = 0; nt < 4; nt++) {
            const int n = n0 + warp_n * 32 + nt * 8 + 2 * (lane & 3);
            if (n < HWP) {
                #pragma unroll
                for (int rr = 0; rr < 2; rr++) {
                    const int mm = mA + rr * 8;
                    float v0 = acc[mt][nt][rr * 2 + 0] + (rr ? biasB : biasA);
                    float v1 = acc[mt][nt][rr * 2 + 1] + (rr ? biasB : biasA);
                    if (MODE == 1) { v0 = gelu_tanh_f(v0); v1 = gelu_tanh_f(v1); }
                    const size_t o = ((size_t)b * M + mm) * HWP + n;
                    if (MODE == 2) {
                        float2 r2 = *reinterpret_cast<const float2*>(&resid[o]);
                        v0 += r2.x; v1 += r2.y;
                    }
                    *reinterpret_cast<float2*>(&out[o]) = make_float2(v0, v1);
                    if (MODE == 0) {
                        s1 += (double)v0 + (double)v1;
                        s2 += (double)v0 * v0 + (double)v1 * v1;
                    }
                }
            }
        }
    }

    if (MODE == 0) {
        #pragma unroll
        for (int off = 16; off > 0; off >>= 1) {
            s1 += __shfl_down_sync(0xffffffff, s1, off);
            s2 += __shfl_down_sync(0xffffffff, s2, off);
        }
        if (lane == 0) { s_red[warp] = s1; s_red[8 + warp] = s2; }
        __syncthreads();
        if (warp == 0) {
            double a1 = (lane < 8) ? s_red[lane] : 0.0;
            double a2 = (lane < 8) ? s_red[8 + lane] : 0.0;
            #pragma unroll
            for (int off = 4; off > 0; off >>= 1) {
                a1 += __shfl_down_sync(0xffffffff, a1, off);
                a2 += __shfl_down_sync(0xffffffff, a2, off);
            }
            if (lane == 0) {
                atomicAdd(&g_red[b * 2 + 0], a1);
                atomicAdd(&g_red[b * 2 + 1], a2);
            }
        }
    }
}

// ---------------- power iteration v3: single sA, transpose-free ----------------
// grid: B*C4 = 6144, block: 128
// u = A v  : 2 threads per row, float4 row reads (pitch 60, 16B-aligned)
// z = A^T u: thread t<56 owns column t -> conflict-free strided column reads
// All cross-lane shuffles executed unconditionally (hang-safe).
__global__ void power_iter_kernel() {
    __shared__ float sA[56 * 60];   // row pitch 60 floats
    __shared__ float sv[64], su[64];
    __shared__ float s_nrm;

    const int bc = blockIdx.x;
    const int t  = threadIdx.x;
    const float* src = g_buf3 + (size_t)bc * HWP;

    // load rows (4 | 56: each float4 stays within one row)
    for (int i = t * 4; i < HWP; i += 512) {
        float4 v = *reinterpret_cast<const float4*>(src + i);
        int r = i / 56, c = i - r * 56;
        *reinterpret_cast<float4*>(&sA[r * 60 + c]) = v;
    }
    if (t < 64) sv[t] = (t < 56) ? 0.1336306f : 0.0f;   // 1/sqrt(56)
    __syncthreads();

    const int r     = t >> 1;            // logical row 0..63
    const int h     = t & 1;             // half: 28 elements
    const bool valid = (r < 56);
    const int rc    = valid ? r : 0;     // clamped in-bounds row for compute

    float nz = 0.0f;
    #pragma unroll
    for (int it = 0; it < 2; it++) {
        // u = A v  (all threads compute; only valid store)
        {
            const float4* row = reinterpret_cast<const float4*>(&sA[rc * 60 + h * 28]);
            const float4* vv  = reinterpret_cast<const float4*>(&sv[h * 28]);
            float s = 0.0f;
            #pragma unroll
            for (int j = 0; j < 7; j++) {
                float4 a4 = row[j], v4 = vv[j];
                s = fmaf(a4.x, v4.x, s); s = fmaf(a4.y, v4.y, s);
                s = fmaf(a4.z, v4.z, s); s = fmaf(a4.w, v4.w, s);
            }
            s += __shfl_xor_sync(0xffffffff, s, 1);
            if (valid && h == 0) su[r] = s;
        }
        __syncthreads();
        // z = A^T u : column-parallel, no shuffle -> guard freely
        if (t < 56) {
            float zc = 0.0f;
            #pragma unroll 8
            for (int j = 0; j < 56; j++)
                zc = fmaf(sA[j * 60 + t], su[j], zc);
            sv[t] = zc;
        }
        __syncthreads();
        // nz = ||z||, normalize
        if (t < 32) {
            float p = sv[t] * sv[t] + ((t < 24) ? sv[t + 32] * sv[t + 32] : 0.0f);
            #pragma unroll
            for (int off = 16; off > 0; off >>= 1)
                p += __shfl_xor_sync(0xffffffff, p, off);
            if (t == 0) s_nrm = sqrtf(p);
        }
        __syncthreads();
        nz = s_nrm;
        if (t < 56) sv[t] = (nz > 0.0f) ? sv[t] / nz : 0.1336306f;
        __syncthreads();
    }
    if (t == 0) {
        float sigma = sqrtf(nz);   // ||A^T A v|| with unit v -> sigma^2
        g_sv[bc] = sigma;
        atomicAdd(&g_svsum, sigma);
    }
}

// ---------------- launch ----------------
extern "C" void kernel_launch(void* const* d_in, const int* in_sizes, int n_in,
                              void* d_out, int out_size) {
    const float* x     = (const float*)d_in[0];
    const float* dw_w  = (const float*)d_in[1];
    const float* dw_b  = (const float*)d_in[2];
    const float* pw_w  = (const float*)d_in[3];
    const float* pw_b  = (const float*)d_in[4];
    const float* ln_w  = (const float*)d_in[5];
    const float* ln_b  = (const float*)d_in[6];
    const float* l1_w  = (const float*)d_in[7];
    const float* l1_b  = (const float*)d_in[8];
    const float* gamma = (const float*)d_in[9];
    const float* beta  = (const float*)d_in[10];
    const float* l2_w  = (const float*)d_in[11];
    const float* l2_b  = (const float*)d_in[12];
    float* out = (float*)d_out;

    float* buf1; cudaGetSymbolAddress((void**)&buf1, g_buf1);
    float* buf2; cudaGetSymbolAddress((void**)&buf2, g_buf2);
    float* buf3; cudaGetSymbolAddress((void**)&buf3, g_buf3);

    const int NB = (HWP + 127) / 128;   // 25

    // 1) depthwise conv -> buf1 (+ zero-init of reductions)
    dw_conv_kernel<<<dim3(1, 7, BB * CC), dim3(56, 8)>>>(x, dw_w, dw_b);

    // 2) pointwise 96->96 -> buf2 (+ fused LN stats)
    gemm_tc<0><<<dim3(NB, 1, BB), 256>>>(pw_w, pw_b, buf1, buf2, CC, CC,
                                         nullptr, nullptr, nullptr);

    // 3) expand 96->384 with fused LN on input + GELU -> buf3
    gemm_tc<1><<<dim3(NB, C4 / 96, BB), 256>>>(l1_w, l1_b, buf2, buf3, C4, CC,
                                               ln_w, ln_b, nullptr);

    // 4) top singular value per slice (+ fused sv sum)
    power_iter_kernel<<<BB * C4, 128>>>();

    // 5) GRN affine + project 384->96 + bias + residual -> out
    gemm_tc<2><<<dim3(NB, 1, BB), 256>>>(l2_w, l2_b, buf3, out, CC, C4,
                                         gamma, beta, x);
}

// round 8
// speedup vs baseline: 2.6244x; 1.0613x over previous
#include <cuda_runtime.h>
#include <math.h>

#define BB   16
#define CC   96
#define C4   384
#define HH   56
#define WW   56
#define HWP  3136          // 56*56
#define CHW  301056        // 96*3136

// fragment-tile sizes (floats)
#define AF_SZ  (4 * 6 * 33 * 4)    // 3168
#define BF_SZ  (4 * 16 * 33 * 2)   // 4224
#define SMEM_DYN ((2 * (AF_SZ + BF_SZ)) * 4)   // 59136 bytes

// ---------------- scratch (device globals; no allocation) ----------------
__device__ float  g_buf1[BB * CC * HWP];   // dw out
__device__ float  g_buf2[BB * CC * HWP];   // pw out (pre-LN)
__device__ float  g_buf3[BB * C4 * HWP];   // expand+gelu out
__device__ double g_red[BB * 2];           // LN sum / sumsq per batch
__device__ float  g_sv[BB * C4];           // top singular values
__device__ float  g_svsum;                 // sum of all sv

// ---------------- helpers ----------------
__device__ __forceinline__ float gelu_tanh_f(float x) {
    const float c = 0.7978845608028654f;
    float x3 = x * x * x;
    return 0.5f * x * (1.0f + tanhf(c * (x + 0.044715f * x3)));
}

__device__ __forceinline__ float tf32r(float x) {
    unsigned u;
    asm("cvt.rna.tf32.f32 %0, %1;" : "=r"(u) : "f"(x));
    return __uint_as_float(u);
}

__device__ __forceinline__ void mma_tf32(float* c, const unsigned* a, const unsigned* b2) {
    asm volatile("mma.sync.aligned.m16n8k8.row.col.f32.tf32.tf32.f32 "
        "{%0,%1,%2,%3}, {%4,%5,%6,%7}, {%8,%9}, {%0,%1,%2,%3};"
        : "+f"(c[0]), "+f"(c[1]), "+f"(c[2]), "+f"(c[3])
        : "r"(a[0]), "r"(a[1]), "r"(a[2]), "r"(a[3]), "r"(b2[0]), "r"(b2[1]));
}

// ---------------- 1) depthwise 7x7 conv + bias (+ scratch zero-init) ----------------
__global__ void dw_conv_kernel(const float* __restrict__ x,
                               const float* __restrict__ dw_w,
                               const float* __restrict__ dw_b) {
    __shared__ float tile[14][62];
    __shared__ float sw[49];

    const int bc = blockIdx.z;
    const int c  = bc % CC;
    const int y0 = blockIdx.y * 8;
    const int tx = threadIdx.x;
    const int ty = threadIdx.y;
    const int tid = ty * 56 + tx;

    if (bc == 0 && blockIdx.y == 0) {
        if (tid < BB * 2) g_red[tid] = 0.0;
        if (tid == BB * 2) g_svsum = 0.0f;
    }

    const float* src = x + (size_t)bc * HWP;
    if (tid < 49) sw[tid] = dw_w[c * 49 + tid];

    for (int i = tid; i < 14 * 62; i += 448) {
        int r  = i / 62;
        int cx = i - r * 62;
        int gy = y0 - 3 + r;
        int gx = cx - 3;
        float v = 0.0f;
        if (gy >= 0 && gy < HH && gx >= 0 && gx < WW) v = src[gy * WW + gx];
        tile[r][cx] = v;
    }
    __syncthreads();

    float acc = dw_b[c];
    #pragma unroll
    for (int dy = 0; dy < 7; dy++)
        #pragma unroll
        for (int dx = 0; dx < 7; dx++)
            acc = fmaf(sw[dy * 7 + dx], tile[ty + dy][tx + dx], acc);

    g_buf1[(size_t)bc * HWP + (y0 + ty) * WW + tx] = acc;
}

// ---------------- TF32 TC GEMM, fragment-order smem, double-buffered, 1 sync/iter ----------------
// out[b,m,n] = sum_k W[m,k]*in[b,k,n]
// MODE 0: +bias, fused LN sum/sumsq reduction             (pointwise)
// MODE 1: LN applied to B at staging, +bias, gelu          (expand)
// MODE 2: B scaled by GRN affine, +bias, +residual         (project)
// grid: (ceil(HW/128), M/96, B), block: 256 (8 warps = 2m x 4n; warp tile 48x32)
template <int MODE>
__global__ __launch_bounds__(256)
void gemm_tc(const float* __restrict__ W,
             const float* __restrict__ bias,
             const float* __restrict__ in,
             float* __restrict__ out,
             int M, int K,
             const float* __restrict__ p0,   // MODE1: ln_w, MODE2: gamma
             const float* __restrict__ p1,   // MODE1: ln_b, MODE2: beta
             const float* __restrict__ resid) {
    extern __shared__ float smem[];
    float* AfB = smem;                      // [2][AF_SZ]
    float* BfB = smem + 2 * AF_SZ;          // [2][BF_SZ]
    __shared__ double s_red[16];

    const int n0 = blockIdx.x * 128;
    const int m0 = blockIdx.y * 96;
    const int b  = blockIdx.z;
    const int tid  = threadIdx.x;
    const int lane = tid & 31;
    const int warp = tid >> 5;
    const int warp_m = warp >> 2;    // 0..1
    const int warp_n = warp & 3;     // 0..3

    const float* inb = in + (size_t)b * K * HWP;
    const float inv_sum = (MODE == 2) ? (1.0f / g_svsum) : 0.0f;

    float mu = 0.0f, rs = 0.0f;
    if (MODE == 1) {
        double m_ = g_red[b * 2 + 0] / (double)CHW;
        double v_ = g_red[b * 2 + 1] / (double)CHW - m_ * m_;
        mu = (float)m_;
        rs = (float)(1.0 / sqrt(v_ + 1e-6));
    }

    float acc[3][4][4];
    #pragma unroll
    for (int mt = 0; mt < 3; mt++)
        #pragma unroll
        for (int nt = 0; nt < 4; nt++)
            #pragma unroll
            for (int j = 0; j < 4; j++) acc[mt][nt][j] = 0.0f;

    const int NK = K >> 5;
    float4 rA[3], rB[4];

    // ---- load tile k0 into registers ----
    auto load_tile = [&](int k0) {
        #pragma unroll
        for (int u = 0; u < 3; u++) {
            int i = tid + u * 256;
            int m = i >> 3, q = i & 7;
            rA[u] = *reinterpret_cast<const float4*>(&W[(size_t)(m0 + m) * K + k0 + q * 4]);
        }
        #pragma unroll
        for (int u = 0; u < 4; u++) {
            int i = tid + u * 256;
            int kk = i >> 5, nq = i & 31;
            int gn = n0 + nq * 4;
            rB[u] = (gn < HWP)
                  ? *reinterpret_cast<const float4*>(&inb[(size_t)(k0 + kk) * HWP + gn])
                  : make_float4(0.f, 0.f, 0.f, 0.f);
        }
    };

    // ---- store registers into fragment-order smem stage (with cvt + transforms) ----
    auto store_tile = [&](int k0, int stage) {
        float* Af = AfB + stage * AF_SZ;
        float* Bf = BfB + stage * BF_SZ;
        #pragma unroll
        for (int u = 0; u < 3; u++) {
            int i = tid + u * 256;
            int m = i >> 3, q = i & 7;
            int ks = q >> 1;
            int mt = m >> 4;
            int g  = m & 7;
            int rp = ((q & 1) << 1) | ((m >> 3) & 1);
            float* dst = &Af[((ks * 6 + mt) * 33 + g * 4) * 4 + rp];
            dst[0]  = tf32r(rA[u].x);
            dst[4]  = tf32r(rA[u].y);
            dst[8]  = tf32r(rA[u].z);
            dst[12] = tf32r(rA[u].w);
        }
        #pragma unroll
        for (int u = 0; u < 4; u++) {
            int i = tid + u * 256;
            int kk = i >> 5, nq = i & 31;
            int gn = n0 + nq * 4;
            float4 v = rB[u];
            if (MODE == 1) {
                if (gn < HWP) {
                    size_t li = (size_t)(k0 + kk) * HWP + gn;
                    float4 lw = *reinterpret_cast<const float4*>(&p0[li]);
                    float4 lb = *reinterpret_cast<const float4*>(&p1[li]);
                    v.x = fmaf((v.x - mu) * rs, lw.x, lb.x);
                    v.y = fmaf((v.y - mu) * rs, lw.y, lb.y);
                    v.z = fmaf((v.z - mu) * rs, lw.z, lb.z);
                    v.w = fmaf((v.w - mu) * rs, lw.w, lb.w);
                }
            }
            if (MODE == 2) {
                int idx = b * C4 + k0 + kk;
                float s  = fmaf(p0[idx] * g_sv[idx], inv_sum, 1.0f);
                float sh = p1[idx];
                v.x = fmaf(v.x, s, sh);
                v.y = fmaf(v.y, s, sh);
                v.z = fmaf(v.z, s, sh);
                v.w = fmaf(v.w, s, sh);
            }
            int ks  = kk >> 3, kin = kk & 7;
            int nt  = nq >> 1;
            float* dst = &Bf[((ks * 16 + nt) * 33 + ((nq & 1) << 4) + (kin & 3)) * 2 + (kin >> 2)];
            dst[0]  = tf32r(v.x);
            dst[8]  = tf32r(v.y);
            dst[16] = tf32r(v.z);
            dst[24] = tf32r(v.w);
        }
    };

    auto compute = [&](int stage) {
        const float* Af = AfB + stage * AF_SZ;
        const float* Bf = BfB + stage * BF_SZ;
        #pragma unroll
        for (int ks = 0; ks < 4; ks++) {
            float4 afr[3];
            #pragma unroll
            for (int mt = 0; mt < 3; mt++)
                afr[mt] = *reinterpret_cast<const float4*>(
                    &Af[((ks * 6 + warp_m * 3 + mt) * 33 + lane) * 4]);
            float2 bfr[4];
            #pragma unroll
            for (int nt = 0; nt < 4; nt++)
                bfr[nt] = *reinterpret_cast<const float2*>(
                    &Bf[((ks * 16 + warp_n * 4 + nt) * 33 + lane) * 2]);
            #pragma unroll
            for (int mt = 0; mt < 3; mt++)
                #pragma unroll
                for (int nt = 0; nt < 4; nt++)
                    mma_tf32(acc[mt][nt],
                             reinterpret_cast<const unsigned*>(&afr[mt]),
                             reinterpret_cast<const unsigned*>(&bfr[nt]));
        }
    };

    // prologue: stage 0
    load_tile(0);
    store_tile(0, 0);
    __syncthreads();

    for (int it = 0; it < NK; it++) {
        const int stage = it & 1;
        if (it + 1 < NK) {
            load_tile((it + 1) << 5);   // LDG in flight during compute
            compute(stage);
            store_tile((it + 1) << 5, stage ^ 1);
        } else {
            compute(stage);
        }
        __syncthreads();
    }

    // ---- epilogue ----
    double s1 = 0.0, s2 = 0.0;
    #pragma unroll
    for (int mt = 0; mt < 3; mt++) {
        const int mA = m0 + warp_m * 48 + mt * 16 + (lane >> 2);
        const float biasA = bias[mA];
        const float biasB = bias[mA + 8];
        #pragma unroll
        for (int nt = 0; nt < 4; nt++) {
            const int n = n0 + warp_n * 32 + nt * 8 + 2 * (lane & 3);
            if (n < HWP) {
                #pragma unroll
                for (int rr = 0; rr < 2; rr++) {
                    const int mm = mA + rr * 8;
                    float v0 = acc[mt][nt][rr * 2 + 0] + (rr ? biasB : biasA);
                    float v1 = acc[mt][nt][rr * 2 + 1] + (rr ? biasB : biasA);
                    if (MODE == 1) { v0 = gelu_tanh_f(v0); v1 = gelu_tanh_f(v1); }
                    const size_t o = ((size_t)b * M + mm) * HWP + n;
                    if (MODE == 2) {
                        float2 r2 = *reinterpret_cast<const float2*>(&resid[o]);
                        v0 += r2.x; v1 += r2.y;
                    }
                    *reinterpret_cast<float2*>(&out[o]) = make_float2(v0, v1);
                    if (MODE == 0) {
                        s1 += (double)v0 + (double)v1;
                        s2 += (double)v0 * v0 + (double)v1 * v1;
                    }
                }
            }
        }
    }

    if (MODE == 0) {
        #pragma unroll
        for (int off = 16; off > 0; off >>= 1) {
            s1 += __shfl_down_sync(0xffffffff, s1, off);
            s2 += __shfl_down_sync(0xffffffff, s2, off);
        }
        if (lane == 0) { s_red[warp] = s1; s_red[8 + warp] = s2; }
        __syncthreads();
        if (warp == 0) {
            double a1 = (lane < 8) ? s_red[lane] : 0.0;
            double a2 = (lane < 8) ? s_red[8 + lane] : 0.0;
            #pragma unroll
            for (int off = 4; off > 0; off >>= 1) {
                a1 += __shfl_down_sync(0xffffffff, a1, off);
                a2 += __shfl_down_sync(0xffffffff, a2, off);
            }
            if (lane == 0) {
                atomicAdd(&g_red[b * 2 + 0], a1);
                atomicAdd(&g_red[b * 2 + 1], a2);
            }
        }
    }
}

// ---------------- power iteration v4: single iteration, transpose-free ----------------
// sigma^2 ~= ||A^T A v0||, v0 = uniform unit vector.
// u = A v0 degenerates to scaled row sums. All shuffles unconditional (hang-safe).
// grid: B*C4 = 6144, block: 128
__global__ void power_iter_kernel() {
    __shared__ float sA[56 * 60];   // row pitch 60 floats
    __shared__ float su[64], sv[64];

    const int bc = blockIdx.x;
    const int t  = threadIdx.x;
    const float* src = g_buf3 + (size_t)bc * HWP;

    for (int i = t * 4; i < HWP; i += 512) {
        float4 v = *reinterpret_cast<const float4*>(src + i);
        int r = i / 56, c = i - r * 56;
        *reinterpret_cast<float4*>(&sA[r * 60 + c]) = v;
    }
    __syncthreads();

    const int r     = t >> 1;            // logical row/col 0..63
    const int h     = t & 1;             // half: 28 elements
    const bool valid = (r < 56);
    const int rc    = valid ? r : 0;     // clamped in-bounds index

    // u = A v0 : scaled half-row sums (float4)
    {
        const float4* row = reinterpret_cast<const float4*>(&sA[rc * 60 + h * 28]);
        float s = 0.0f;
        #pragma unroll
        for (int j = 0; j < 7; j++) {
            float4 a4 = row[j];
            s += a4.x + a4.y + a4.z + a4.w;
        }
        s += __shfl_xor_sync(0xffffffff, s, 1);
        if (valid && h == 0) su[r] = s * 0.1336306f;   // * 1/sqrt(56)
    }
    __syncthreads();

    // z = A^T u : 2 threads per column, 28 terms each; half-warps hit
    // disjoint bank halves (1680 % 32 == 16) -> conflict-free.
    {
        float s = 0.0f;
        const float* col = &sA[h * 28 * 60 + rc];
        const float* uu  = &su[h * 28];
        #pragma unroll
        for (int j = 0; j < 28; j++)
            s = fmaf(col[j * 60], uu[j], s);
        s += __shfl_xor_sync(0xffffffff, s, 1);
        if (valid && h == 0) sv[r] = s;
    }
    __syncthreads();

    // sigma = sqrt(||z||) ; ||z|| ~= sigma^2
    if (t < 32) {
        float p = sv[t] * sv[t] + ((t < 24) ? sv[t + 32] * sv[t + 32] : 0.0f);
        #pragma unroll
        for (int off = 16; off > 0; off >>= 1)
            p += __shfl_xor_sync(0xffffffff, p, off);
        if (t == 0) {
            float sigma = sqrtf(sqrtf(p));
            g_sv[bc] = sigma;
            atomicAdd(&g_svsum, sigma);
        }
    }
}

// ---------------- launch ----------------
extern "C" void kernel_launch(void* const* d_in, const int* in_sizes, int n_in,
                              void* d_out, int out_size) {
    const float* x     = (const float*)d_in[0];
    const float* dw_w  = (const float*)d_in[1];
    const float* dw_b  = (const float*)d_in[2];
    const float* pw_w  = (const float*)d_in[3];
    const float* pw_b  = (const float*)d_in[4];
    const float* ln_w  = (const float*)d_in[5];
    const float* ln_b  = (const float*)d_in[6];
    const float* l1_w  = (const float*)d_in[7];
    const float* l1_b  = (const float*)d_in[8];
    const float* gamma = (const float*)d_in[9];
    const float* beta  = (const float*)d_in[10];
    const float* l2_w  = (const float*)d_in[11];
    const float* l2_b  = (const float*)d_in[12];
    float* out = (float*)d_out;

    float* buf1; cudaGetSymbolAddress((void**)&buf1, g_buf1);
    float* buf2; cudaGetSymbolAddress((void**)&buf2, g_buf2);
    float* buf3; cudaGetSymbolAddress((void**)&buf3, g_buf3);

    // raise dynamic smem limit (idempotent host-side attribute set)
    cudaFuncSetAttribute(gemm_tc<0>, cudaFuncAttributeMaxDynamicSharedMemorySize, SMEM_DYN);
    cudaFuncSetAttribute(gemm_tc<1>, cudaFuncAttributeMaxDynamicSharedMemorySize, SMEM_DYN);
    cudaFuncSetAttribute(gemm_tc<2>, cudaFuncAttributeMaxDynamicSharedMemorySize, SMEM_DYN);

    const int NB = (HWP + 127) / 128;   // 25

    // 1) depthwise conv -> buf1 (+ zero-init of reductions)
    dw_conv_kernel<<<dim3(1, 7, BB * CC), dim3(56, 8)>>>(x, dw_w, dw_b);

    // 2) pointwise 96->96 -> buf2 (+ fused LN stats)
    gemm_tc<0><<<dim3(NB, 1, BB), 256, SMEM_DYN>>>(pw_w, pw_b, buf1, buf2, CC, CC,
                                                   nullptr, nullptr, nullptr);

    // 3) expand 96->384 with fused LN on input + GELU -> buf3
    gemm_tc<1><<<dim3(NB, C4 / 96, BB), 256, SMEM_DYN>>>(l1_w, l1_b, buf2, buf3, C4, CC,
                                                         ln_w, ln_b, nullptr);

    // 4) top singular value per slice (+ fused sv sum)
    power_iter_kernel<<<BB * C4, 128>>>();

    // 5) GRN affine + project 384->96 + bias + residual -> out
    gemm_tc<2><<<dim3(NB, 1, BB), 256, SMEM_DYN>>>(l2_w, l2_b, buf3, out, CC, C4,
                                                   gamma, beta, x);
}